// round 3
// baseline (speedup 1.0000x reference)
#include <cuda_runtime.h>
#include <cuda_bf16.h>

#define N_NODES 100000
#define N_EDGES 1600000
#define F 64
#define NUM_GRAPHS 64
#define TOPO_DIM 16
#define NUM_CLASSES 4

// Scratch (device globals; allocation-free per harness rules)
__device__ float g_deg[N_NODES];
__device__ float g_dis[N_NODES];
__device__ float g_bufA[N_NODES * F];   // xs (layer1), then xs2 (layer2)
__device__ float g_bufB[N_NODES * F];   // agg1 (zeroed at init)
__device__ float g_bufC[N_NODES * F];   // agg2 (zeroed at init)
__device__ float g_gsum[NUM_GRAPHS * F];
__device__ float g_gcnt[NUM_GRAPHS];

// ---------------- init: zero all accumulators ----------------
__global__ void k_init() {
    int i = blockIdx.x * blockDim.x + threadIdx.x;   // 0 .. N*F-1
    if (i < N_NODES * F) {
        g_bufB[i] = 0.0f;
        g_bufC[i] = 0.0f;
    }
    if (i < N_NODES) g_deg[i] = 0.0f;
    if (i < NUM_GRAPHS * F) g_gsum[i] = 0.0f;
    if (i < NUM_GRAPHS) g_gcnt[i] = 0.0f;
}

// ---------------- degree ----------------
__global__ void k_degree(const int* __restrict__ edge) {
    int e = blockIdx.x * blockDim.x + threadIdx.x;
    if (e < N_EDGES) {
        int dst = edge[N_EDGES + e];
        atomicAdd(&g_deg[dst], 1.0f);
    }
}

__global__ void k_dis() {
    int i = blockIdx.x * blockDim.x + threadIdx.x;
    if (i < N_NODES) g_dis[i] = rsqrtf(g_deg[i] + 1.0f);
}

// ---------------- GEMM1: xs = (x @ W1) * dis ----------------
// 256 threads, 4 rows per block. W1 (64x64) staged in smem.
__global__ void k_gemm1(const float* __restrict__ x, const float* __restrict__ W) {
    __shared__ float Ws[F * F];
    __shared__ float Xs[4 * F];
    int tid = threadIdx.x;
    #pragma unroll
    for (int i = tid; i < F * F; i += 256) Ws[i] = W[i];
    int base = blockIdx.x * 4;
    int r = tid >> 6, c = tid & 63;
    Xs[tid] = x[(base + r) * F + c];
    __syncthreads();
    float acc = 0.0f;
    #pragma unroll
    for (int k = 0; k < F; k++) acc = fmaf(Xs[r * F + k], Ws[k * F + c], acc);
    int row = base + r;
    g_bufA[row * F + c] = acc * g_dis[row];
}

// ---------------- scatter: agg[dst] += xs[src]  (16 lanes x float4 per edge) ----
__global__ void k_scatter1(const int* __restrict__ edge) {
    long long gid = (long long)blockIdx.x * blockDim.x + threadIdx.x;
    int e = (int)(gid >> 4);
    int lane = (int)(gid & 15);
    if (e >= N_EDGES) return;
    int src = __ldg(&edge[e]);
    int dst = __ldg(&edge[N_EDGES + e]);
    float4 v = *reinterpret_cast<const float4*>(g_bufA + (long long)src * F + lane * 4);
    float* d = g_bufB + (long long)dst * F + lane * 4;
    atomicAdd(d + 0, v.x);
    atomicAdd(d + 1, v.y);
    atomicAdd(d + 2, v.z);
    atomicAdd(d + 3, v.w);
}

__global__ void k_scatter2(const int* __restrict__ edge) {
    long long gid = (long long)blockIdx.x * blockDim.x + threadIdx.x;
    int e = (int)(gid >> 4);
    int lane = (int)(gid & 15);
    if (e >= N_EDGES) return;
    int src = __ldg(&edge[e]);
    int dst = __ldg(&edge[N_EDGES + e]);
    float4 v = *reinterpret_cast<const float4*>(g_bufA + (long long)src * F + lane * 4);
    float* d = g_bufC + (long long)dst * F + lane * 4;
    atomicAdd(d + 0, v.x);
    atomicAdd(d + 1, v.y);
    atomicAdd(d + 2, v.z);
    atomicAdd(d + 3, v.w);
}

// ---------------- GEMM2 fused: h = relu(dis*(agg1+xs1)+b1); xs2 = (h @ W2)*dis
__global__ void k_gemm2(const float* __restrict__ W, const float* __restrict__ b1) {
    __shared__ float Ws[F * F];
    __shared__ float Hs[4 * F];
    int tid = threadIdx.x;
    #pragma unroll
    for (int i = tid; i < F * F; i += 256) Ws[i] = W[i];
    int base = blockIdx.x * 4;
    int r = tid >> 6, c = tid & 63;
    int row = base + r;
    float dis = g_dis[row];
    float h = dis * (g_bufB[row * F + c] + g_bufA[row * F + c]) + b1[c];
    Hs[tid] = fmaxf(h, 0.0f);
    __syncthreads();
    float acc = 0.0f;
    #pragma unroll
    for (int k = 0; k < F; k++) acc = fmaf(Hs[r * F + k], Ws[k * F + c], acc);
    g_bufA[row * F + c] = acc * dis;   // xs2 (all reads of bufA row done above)
}

// ---------------- finish layer2 + mean-pool accumulate ----------------
__global__ void k_finish_pool(const float* __restrict__ b2,
                              const int* __restrict__ batch) {
    int i = blockIdx.x * blockDim.x + threadIdx.x;   // node*64 + feat
    if (i >= N_NODES * F) return;
    int node = i >> 6, j = i & 63;
    float dis = g_dis[node];
    float h = dis * (g_bufC[i] + g_bufA[i]) + b2[j];
    h = fmaxf(h, 0.0f);
    int g = batch[node];
    atomicAdd(&g_gsum[g * F + j], h);
    if (j == 0) atomicAdd(&g_gcnt[g], 1.0f);
}

// ---------------- head: out = [g, topo] @ Wlin + blin ----------------
__global__ void k_head(const float* __restrict__ topo, const float* __restrict__ Wlin,
                       const float* __restrict__ blin, float* __restrict__ out) {
    int t = threadIdx.x;                   // 256 threads = 64 graphs x 4 classes
    int g = t >> 2, c = t & 3;
    float cnt = fmaxf(g_gcnt[g], 1.0f);
    float inv = 1.0f / cnt;
    float acc = blin[c];
    #pragma unroll
    for (int k = 0; k < F; k++)
        acc = fmaf(g_gsum[g * F + k] * inv, Wlin[k * NUM_CLASSES + c], acc);
    #pragma unroll
    for (int k = 0; k < TOPO_DIM; k++)
        acc = fmaf(topo[g * TOPO_DIM + k], Wlin[(F + k) * NUM_CLASSES + c], acc);
    out[g * NUM_CLASSES + c] = acc;
}

extern "C" void kernel_launch(void* const* d_in, const int* in_sizes, int n_in,
                              void* d_out, int out_size) {
    const float* x    = (const float*)d_in[0];
    const int*   edge = (const int*)d_in[1];
    const int*   batch= (const int*)d_in[2];
    const float* topo = (const float*)d_in[3];
    const float* W1   = (const float*)d_in[4];
    const float* b1   = (const float*)d_in[5];
    const float* W2   = (const float*)d_in[6];
    const float* b2   = (const float*)d_in[7];
    const float* Wlin = (const float*)d_in[8];
    const float* blin = (const float*)d_in[9];
    float* out = (float*)d_out;

    const int NF = N_NODES * F;
    const long long total = (long long)N_EDGES * 16;
    const int sblocks = (int)((total + 255) / 256);

    k_init<<<(NF + 255) / 256, 256>>>();
    k_degree<<<(N_EDGES + 255) / 256, 256>>>(edge);
    k_dis<<<(N_NODES + 255) / 256, 256>>>();
    k_gemm1<<<N_NODES / 4, 256>>>(x, W1);
    k_scatter1<<<sblocks, 256>>>(edge);
    k_gemm2<<<N_NODES / 4, 256>>>(W2, b1);
    k_scatter2<<<sblocks, 256>>>(edge);
    k_finish_pool<<<(NF + 255) / 256, 256>>>(b2, batch);
    k_head<<<1, 256>>>(topo, Wlin, blin, out);
}

// round 4
// speedup vs baseline: 1.8844x; 1.8844x over previous
#include <cuda_runtime.h>
#include <cuda_bf16.h>

#define N_NODES 100000
#define N_EDGES 1600000
#define F 64
#define NUM_GRAPHS 64
#define TOPO_DIM 16
#define NUM_CLASSES 4

// Scratch (device globals; allocation-free per harness rules)
__device__ float g_deg[N_NODES];
__device__ float g_dis[N_NODES];
__device__ float g_bufA[N_NODES * F];   // xs (layer1), then xs2 (layer2)
__device__ float g_bufB[N_NODES * F];   // agg1 (zeroed at init)
__device__ float g_bufC[N_NODES * F];   // agg2 (zeroed at init)
__device__ float g_gsum[NUM_GRAPHS * F];
__device__ float g_gcnt[NUM_GRAPHS];

// ---------------- init: zero all accumulators ----------------
__global__ void k_init() {
    int i = blockIdx.x * blockDim.x + threadIdx.x;
    if (i < N_NODES * F) {
        g_bufB[i] = 0.0f;
        g_bufC[i] = 0.0f;
    }
    if (i < N_NODES) g_deg[i] = 0.0f;
    if (i < NUM_GRAPHS * F) g_gsum[i] = 0.0f;
    if (i < NUM_GRAPHS) g_gcnt[i] = 0.0f;
}

// ---------------- degree ----------------
__global__ void k_degree(const int* __restrict__ edge) {
    int e = blockIdx.x * blockDim.x + threadIdx.x;
    if (e < N_EDGES) atomicAdd(&g_deg[edge[N_EDGES + e]], 1.0f);
}

// dis = rsqrt(deg+1); also accumulate per-graph node counts
__global__ void k_dis(const int* __restrict__ batch) {
    int i = blockIdx.x * blockDim.x + threadIdx.x;
    if (i < N_NODES) {
        g_dis[i] = rsqrtf(g_deg[i] + 1.0f);
        atomicAdd(&g_gcnt[batch[i]], 1.0f);
    }
}

// ---------------- GEMM1: xs = (x @ W1) * dis ----------------
// 256 threads, 16 rows/block, 4 output cols per thread (float4 LDS on W).
__global__ void k_gemm1(const float* __restrict__ x, const float* __restrict__ W) {
    __shared__ float Ws[F * F];
    __shared__ float Xs[16 * F];
    int tid = threadIdx.x;
    float4* Wv = (float4*)Ws;
    const float4* Wg = (const float4*)W;
    #pragma unroll
    for (int i = 0; i < 4; i++) Wv[tid + 256 * i] = Wg[tid + 256 * i];
    int base = blockIdx.x * 16;
    ((float4*)Xs)[tid] = ((const float4*)(x + (long long)base * F))[tid];
    __syncthreads();
    int r = tid >> 4;
    int c4 = tid & 15;
    float a0 = 0, a1 = 0, a2 = 0, a3 = 0;
    #pragma unroll
    for (int k = 0; k < F; k++) {
        float xv = Xs[r * F + k];
        float4 w = ((float4*)Ws)[k * 16 + c4];
        a0 = fmaf(xv, w.x, a0);
        a1 = fmaf(xv, w.y, a1);
        a2 = fmaf(xv, w.z, a2);
        a3 = fmaf(xv, w.w, a3);
    }
    int row = base + r;
    float dis = g_dis[row];
    float4 o = make_float4(a0 * dis, a1 * dis, a2 * dis, a3 * dis);
    ((float4*)g_bufA)[row * 16 + c4] = o;
}

// ---------------- scatter: agg[dst] += xs[src]  (16 lanes x red.v4 per edge) ----
template<int WHICH>
__global__ void k_scatter(const int* __restrict__ edge) {
    long long gid = (long long)blockIdx.x * blockDim.x + threadIdx.x;
    int e = (int)(gid >> 4);
    int lane = (int)(gid & 15);
    if (e >= N_EDGES) return;
    int src = __ldg(&edge[e]);
    int dst = __ldg(&edge[N_EDGES + e]);
    float4 v = *reinterpret_cast<const float4*>(g_bufA + (long long)src * F + lane * 4);
    float* d = (WHICH == 0 ? g_bufB : g_bufC) + (long long)dst * F + lane * 4;
    unsigned long long ga;
    asm("cvta.to.global.u64 %0, %1;" : "=l"(ga) : "l"(d));
    asm volatile("red.global.add.v4.f32 [%0], {%1,%2,%3,%4};"
                 :: "l"(ga), "f"(v.x), "f"(v.y), "f"(v.z), "f"(v.w) : "memory");
}

// ---------------- GEMM2 fused: h = relu(dis*(agg1+xs1)+b1); xs2 = (h @ W2)*dis
__global__ void k_gemm2(const float* __restrict__ W, const float* __restrict__ b1) {
    __shared__ float Ws[F * F];
    __shared__ float Hs[16 * F];
    int tid = threadIdx.x;
    float4* Wv = (float4*)Ws;
    const float4* Wg = (const float4*)W;
    #pragma unroll
    for (int i = 0; i < 4; i++) Wv[tid + 256 * i] = Wg[tid + 256 * i];
    int base = blockIdx.x * 16;
    // compute relu row chunk: thread handles row r, cols c4*4..c4*4+3
    int r = tid >> 4;
    int c4 = tid & 15;
    int row = base + r;
    float dis = g_dis[row];
    float4 agg = ((const float4*)g_bufB)[row * 16 + c4];
    float4 xs  = ((const float4*)g_bufA)[row * 16 + c4];
    const float4 bb = ((const float4*)b1)[c4];
    float4 h;
    h.x = fmaxf(dis * (agg.x + xs.x) + bb.x, 0.0f);
    h.y = fmaxf(dis * (agg.y + xs.y) + bb.y, 0.0f);
    h.z = fmaxf(dis * (agg.z + xs.z) + bb.z, 0.0f);
    h.w = fmaxf(dis * (agg.w + xs.w) + bb.w, 0.0f);
    ((float4*)Hs)[r * 16 + c4] = h;
    __syncthreads();
    float a0 = 0, a1 = 0, a2 = 0, a3 = 0;
    #pragma unroll
    for (int k = 0; k < F; k++) {
        float xv = Hs[r * F + k];
        float4 w = ((float4*)Ws)[k * 16 + c4];
        a0 = fmaf(xv, w.x, a0);
        a1 = fmaf(xv, w.y, a1);
        a2 = fmaf(xv, w.z, a2);
        a3 = fmaf(xv, w.w, a3);
    }
    float4 o = make_float4(a0 * dis, a1 * dis, a2 * dis, a3 * dis);
    ((float4*)g_bufA)[row * 16 + c4] = o;   // xs2 (all bufA reads done above)
}

// ---------------- finish layer2 + segmented mean-pool ----------------
// block = 256 threads, 64 nodes. thread t: feat j=t&63, node-chunk s=t>>6
// serial over 16 nodes; atomic flush only on graph-boundary (batch sorted).
__global__ void k_finish_pool(const float* __restrict__ b2,
                              const int* __restrict__ batch) {
    int tid = threadIdx.x;
    int j = tid & 63;
    int s = tid >> 6;
    int base = blockIdx.x * 64 + s * 16;
    if (base >= N_NODES) return;
    float bj = b2[j];
    int curg = batch[base];
    float acc = 0.0f;
    #pragma unroll 4
    for (int i = 0; i < 16; i++) {
        int node = base + i;
        if (node >= N_NODES) break;
        int g = batch[node];
        if (g != curg) {
            atomicAdd(&g_gsum[curg * F + j], acc);
            acc = 0.0f;
            curg = g;
        }
        float dis = g_dis[node];
        float h = fmaxf(dis * (g_bufC[node * F + j] + g_bufA[node * F + j]) + bj, 0.0f);
        acc += h;
    }
    atomicAdd(&g_gsum[curg * F + j], acc);
}

// ---------------- head: out = [g, topo] @ Wlin + blin ----------------
__global__ void k_head(const float* __restrict__ topo, const float* __restrict__ Wlin,
                       const float* __restrict__ blin, float* __restrict__ out) {
    int t = threadIdx.x;                   // 256 threads = 64 graphs x 4 classes
    int g = t >> 2, c = t & 3;
    float inv = 1.0f / fmaxf(g_gcnt[g], 1.0f);
    float acc = blin[c];
    #pragma unroll
    for (int k = 0; k < F; k++)
        acc = fmaf(g_gsum[g * F + k] * inv, Wlin[k * NUM_CLASSES + c], acc);
    #pragma unroll
    for (int k = 0; k < TOPO_DIM; k++)
        acc = fmaf(topo[g * TOPO_DIM + k], Wlin[(F + k) * NUM_CLASSES + c], acc);
    out[g * NUM_CLASSES + c] = acc;
}

extern "C" void kernel_launch(void* const* d_in, const int* in_sizes, int n_in,
                              void* d_out, int out_size) {
    const float* x    = (const float*)d_in[0];
    const int*   edge = (const int*)d_in[1];
    const int*   batch= (const int*)d_in[2];
    const float* topo = (const float*)d_in[3];
    const float* W1   = (const float*)d_in[4];
    const float* b1   = (const float*)d_in[5];
    const float* W2   = (const float*)d_in[6];
    const float* b2   = (const float*)d_in[7];
    const float* Wlin = (const float*)d_in[8];
    const float* blin = (const float*)d_in[9];
    float* out = (float*)d_out;

    const int NF = N_NODES * F;
    const long long total = (long long)N_EDGES * 16;
    const int sblocks = (int)((total + 255) / 256);

    k_init<<<(NF + 255) / 256, 256>>>();
    k_degree<<<(N_EDGES + 255) / 256, 256>>>(edge);
    k_dis<<<(N_NODES + 255) / 256, 256>>>(batch);
    k_gemm1<<<N_NODES / 16, 256>>>(x, W1);        // 100000/16 = 6250 exact
    k_scatter<0><<<sblocks, 256>>>(edge);
    k_gemm2<<<N_NODES / 16, 256>>>(W2, b1);
    k_scatter<1><<<sblocks, 256>>>(edge);
    k_finish_pool<<<(N_NODES + 63) / 64, 256>>>(b2, batch);
    k_head<<<1, 256>>>(topo, Wlin, blin, out);
}

// round 5
// speedup vs baseline: 2.3827x; 1.2644x over previous
#include <cuda_runtime.h>
#include <cuda_bf16.h>

#define N_NODES 100000
#define N_EDGES 1600000
#define F 64
#define NUM_GRAPHS 64
#define TOPO_DIM 16
#define NUM_CLASSES 4

#define SCAN_BLK 512
#define SCAN_NBLK ((N_NODES + SCAN_BLK - 1) / SCAN_BLK)   // 196

// Scratch (device globals; allocation-free per harness rules)
__device__ int   g_cnt[N_NODES];        // in-degree (no self loop)
__device__ int   g_rowptr[N_NODES];     // CSR row start
__device__ int   g_fill[N_NODES];       // mutable fill cursor
__device__ int   g_srcs[N_EDGES];       // CSR column (src) array
__device__ int   g_lscan[N_NODES];      // block-local exclusive scan
__device__ int   g_bsum[SCAN_NBLK];
__device__ int   g_boff[SCAN_NBLK];
__device__ float g_dis[N_NODES];
__device__ float g_bufA[N_NODES * F];   // xs (layer1), then xs2 (layer2)
__device__ float g_bufB[N_NODES * F];   // agg1
__device__ float g_bufC[N_NODES * F];   // agg2
__device__ float g_gsum[NUM_GRAPHS * F];
__device__ float g_gcnt[NUM_GRAPHS];

// ---------------- init ----------------
__global__ void k_init() {
    int i = blockIdx.x * blockDim.x + threadIdx.x;
    if (i < N_NODES) g_cnt[i] = 0;
    if (i < NUM_GRAPHS * F) g_gsum[i] = 0.0f;
    if (i < NUM_GRAPHS) g_gcnt[i] = 0.0f;
}

// ---------------- degree histogram ----------------
__global__ void k_degree(const int* __restrict__ edge) {
    int e = blockIdx.x * blockDim.x + threadIdx.x;
    if (e < N_EDGES) atomicAdd(&g_cnt[edge[N_EDGES + e]], 1);
}

// dis = rsqrt(deg+1); also per-graph node counts
__global__ void k_dis(const int* __restrict__ batch) {
    int i = blockIdx.x * blockDim.x + threadIdx.x;
    if (i < N_NODES) {
        g_dis[i] = rsqrtf((float)g_cnt[i] + 1.0f);
        atomicAdd(&g_gcnt[batch[i]], 1.0f);
    }
}

// ---------------- prefix scan (3 kernels) ----------------
__global__ void k_scan1() {
    __shared__ int s[SCAN_BLK];
    int t = threadIdx.x;
    int i = blockIdx.x * SCAN_BLK + t;
    int v = (i < N_NODES) ? g_cnt[i] : 0;
    s[t] = v;
    __syncthreads();
    #pragma unroll
    for (int off = 1; off < SCAN_BLK; off <<= 1) {
        int add = (t >= off) ? s[t - off] : 0;
        __syncthreads();
        s[t] += add;
        __syncthreads();
    }
    if (i < N_NODES) g_lscan[i] = s[t] - v;   // exclusive
    if (t == SCAN_BLK - 1) g_bsum[blockIdx.x] = s[t];
}

__global__ void k_scan2() {
    __shared__ int s[256];
    int t = threadIdx.x;
    int v = (t < SCAN_NBLK) ? g_bsum[t] : 0;
    s[t] = v;
    __syncthreads();
    #pragma unroll
    for (int off = 1; off < 256; off <<= 1) {
        int add = (t >= off) ? s[t - off] : 0;
        __syncthreads();
        s[t] += add;
        __syncthreads();
    }
    if (t < SCAN_NBLK) g_boff[t] = s[t] - v;  // exclusive
}

__global__ void k_scan3() {
    int i = blockIdx.x * blockDim.x + threadIdx.x;
    if (i < N_NODES) {
        int rp = g_lscan[i] + g_boff[i / SCAN_BLK];
        g_rowptr[i] = rp;
        g_fill[i] = rp;
    }
}

// ---------------- bin edges by dst ----------------
__global__ void k_bin(const int* __restrict__ edge) {
    int e = blockIdx.x * blockDim.x + threadIdx.x;
    if (e < N_EDGES) {
        int src = edge[e];
        int dst = edge[N_EDGES + e];
        int pos = atomicAdd(&g_fill[dst], 1);
        g_srcs[pos] = src;
    }
}

// ---------------- GEMM1: xs = (x @ W1) * dis ----------------
// 256 threads, 64 rows/block, thread computes 4 rows x 4 cols.
__global__ void k_gemm1(const float* __restrict__ x, const float* __restrict__ W) {
    __shared__ float Ws[F * F];      // 16KB
    __shared__ float Xs[64 * F];     // 16KB
    int tid = threadIdx.x;
    float4* Wv = (float4*)Ws;
    const float4* Wg = (const float4*)W;
    #pragma unroll
    for (int i = 0; i < 4; i++) Wv[tid + 256 * i] = Wg[tid + 256 * i];
    int base = blockIdx.x * 64;
    // load 64 rows of x (1024 float4, 4 per thread)
    #pragma unroll
    for (int i = 0; i < 4; i++) {
        int idx = tid + 256 * i;                 // row-chunk idx: row=idx>>4
        int row = base + (idx >> 4);
        ((float4*)Xs)[idx] = (row < N_NODES)
            ? ((const float4*)x)[(long long)row * 16 + (idx & 15)]
            : make_float4(0.f, 0.f, 0.f, 0.f);
    }
    __syncthreads();
    int r4 = tid >> 4;        // 0..15 -> rows r4*4 .. r4*4+3
    int c4 = tid & 15;        // float4 column
    float4 acc[4] = {};
    #pragma unroll
    for (int k = 0; k < F; k++) {
        float4 w = ((float4*)Ws)[k * 16 + c4];
        #pragma unroll
        for (int i = 0; i < 4; i++) {
            float xv = Xs[(r4 * 4 + i) * F + k];
            acc[i].x = fmaf(xv, w.x, acc[i].x);
            acc[i].y = fmaf(xv, w.y, acc[i].y);
            acc[i].z = fmaf(xv, w.z, acc[i].z);
            acc[i].w = fmaf(xv, w.w, acc[i].w);
        }
    }
    #pragma unroll
    for (int i = 0; i < 4; i++) {
        int row = base + r4 * 4 + i;
        if (row < N_NODES) {
            float dis = g_dis[row];
            float4 o = make_float4(acc[i].x * dis, acc[i].y * dis,
                                   acc[i].z * dis, acc[i].w * dis);
            ((float4*)g_bufA)[row * 16 + c4] = o;
        }
    }
}

// ---------------- CSR aggregation: agg[n] = sum_{src in bin(n)} xs[src] ----
// 16 lanes per node (float4 each). No atomics.
template<int WHICH>
__global__ void k_agg() {
    long long gid = (long long)blockIdx.x * blockDim.x + threadIdx.x;
    int node = (int)(gid >> 4);
    int lane = (int)(gid & 15);
    if (node >= N_NODES) return;
    int beg = g_rowptr[node];
    int cnt = g_cnt[node];
    float4 acc = make_float4(0.f, 0.f, 0.f, 0.f);
    for (int i = 0; i < cnt; i++) {
        int src = __ldg(&g_srcs[beg + i]);
        float4 v = *reinterpret_cast<const float4*>(g_bufA + (long long)src * F + lane * 4);
        acc.x += v.x; acc.y += v.y; acc.z += v.z; acc.w += v.w;
    }
    float* dstbuf = (WHICH == 0) ? g_bufB : g_bufC;
    ((float4*)dstbuf)[(long long)node * 16 + lane] = acc;
}

// ---------------- GEMM2 fused: h = relu(dis*(agg1+xs1)+b1); xs2 = (h @ W2)*dis
__global__ void k_gemm2(const float* __restrict__ W, const float* __restrict__ b1) {
    __shared__ float Ws[F * F];
    __shared__ float Hs[64 * F];
    int tid = threadIdx.x;
    float4* Wv = (float4*)Ws;
    const float4* Wg = (const float4*)W;
    #pragma unroll
    for (int i = 0; i < 4; i++) Wv[tid + 256 * i] = Wg[tid + 256 * i];
    int base = blockIdx.x * 64;
    // compute relu rows into Hs (4 float4 chunks per thread)
    #pragma unroll
    for (int i = 0; i < 4; i++) {
        int idx = tid + 256 * i;
        int row = base + (idx >> 4);
        int c = idx & 15;
        float4 h = make_float4(0.f, 0.f, 0.f, 0.f);
        if (row < N_NODES) {
            float dis = g_dis[row];
            float4 agg = ((const float4*)g_bufB)[(long long)row * 16 + c];
            float4 xs  = ((const float4*)g_bufA)[(long long)row * 16 + c];
            float4 bb  = ((const float4*)b1)[c];
            h.x = fmaxf(dis * (agg.x + xs.x) + bb.x, 0.0f);
            h.y = fmaxf(dis * (agg.y + xs.y) + bb.y, 0.0f);
            h.z = fmaxf(dis * (agg.z + xs.z) + bb.z, 0.0f);
            h.w = fmaxf(dis * (agg.w + xs.w) + bb.w, 0.0f);
        }
        ((float4*)Hs)[idx] = h;
    }
    __syncthreads();
    int r4 = tid >> 4;
    int c4 = tid & 15;
    float4 acc[4] = {};
    #pragma unroll
    for (int k = 0; k < F; k++) {
        float4 w = ((float4*)Ws)[k * 16 + c4];
        #pragma unroll
        for (int i = 0; i < 4; i++) {
            float xv = Hs[(r4 * 4 + i) * F + k];
            acc[i].x = fmaf(xv, w.x, acc[i].x);
            acc[i].y = fmaf(xv, w.y, acc[i].y);
            acc[i].z = fmaf(xv, w.z, acc[i].z);
            acc[i].w = fmaf(xv, w.w, acc[i].w);
        }
    }
    #pragma unroll
    for (int i = 0; i < 4; i++) {
        int row = base + r4 * 4 + i;
        if (row < N_NODES) {
            float dis = g_dis[row];
            float4 o = make_float4(acc[i].x * dis, acc[i].y * dis,
                                   acc[i].z * dis, acc[i].w * dis);
            ((float4*)g_bufA)[row * 16 + c4] = o;   // xs2
        }
    }
}

// ---------------- finish layer2 + segmented mean-pool ----------------
__global__ void k_finish_pool(const float* __restrict__ b2,
                              const int* __restrict__ batch) {
    int tid = threadIdx.x;
    int j = tid & 63;
    int s = tid >> 6;
    int base = blockIdx.x * 64 + s * 16;
    if (base >= N_NODES) return;
    float bj = b2[j];
    int curg = batch[base];
    float acc = 0.0f;
    #pragma unroll 4
    for (int i = 0; i < 16; i++) {
        int node = base + i;
        if (node >= N_NODES) break;
        int g = batch[node];
        if (g != curg) {
            atomicAdd(&g_gsum[curg * F + j], acc);
            acc = 0.0f;
            curg = g;
        }
        float dis = g_dis[node];
        float h = fmaxf(dis * (g_bufC[node * F + j] + g_bufA[node * F + j]) + bj, 0.0f);
        acc += h;
    }
    atomicAdd(&g_gsum[curg * F + j], acc);
}

// ---------------- head ----------------
__global__ void k_head(const float* __restrict__ topo, const float* __restrict__ Wlin,
                       const float* __restrict__ blin, float* __restrict__ out) {
    int t = threadIdx.x;                   // 64 graphs x 4 classes
    int g = t >> 2, c = t & 3;
    float inv = 1.0f / fmaxf(g_gcnt[g], 1.0f);
    float acc = blin[c];
    #pragma unroll
    for (int k = 0; k < F; k++)
        acc = fmaf(g_gsum[g * F + k] * inv, Wlin[k * NUM_CLASSES + c], acc);
    #pragma unroll
    for (int k = 0; k < TOPO_DIM; k++)
        acc = fmaf(topo[g * TOPO_DIM + k], Wlin[(F + k) * NUM_CLASSES + c], acc);
    out[g * NUM_CLASSES + c] = acc;
}

extern "C" void kernel_launch(void* const* d_in, const int* in_sizes, int n_in,
                              void* d_out, int out_size) {
    const float* x    = (const float*)d_in[0];
    const int*   edge = (const int*)d_in[1];
    const int*   batch= (const int*)d_in[2];
    const float* topo = (const float*)d_in[3];
    const float* W1   = (const float*)d_in[4];
    const float* b1   = (const float*)d_in[5];
    const float* W2   = (const float*)d_in[6];
    const float* b2   = (const float*)d_in[7];
    const float* Wlin = (const float*)d_in[8];
    const float* blin = (const float*)d_in[9];
    float* out = (float*)d_out;

    const long long aggtotal = (long long)N_NODES * 16;
    const int ablocks = (int)((aggtotal + 255) / 256);
    const int gblocks = (N_NODES + 63) / 64;   // 1563

    k_init<<<(N_NODES + 255) / 256, 256>>>();
    k_degree<<<(N_EDGES + 255) / 256, 256>>>(edge);
    k_dis<<<(N_NODES + 255) / 256, 256>>>(batch);
    k_scan1<<<SCAN_NBLK, SCAN_BLK>>>();
    k_scan2<<<1, 256>>>();
    k_scan3<<<(N_NODES + 255) / 256, 256>>>();
    k_bin<<<(N_EDGES + 255) / 256, 256>>>(edge);

    k_gemm1<<<gblocks, 256>>>(x, W1);
    k_agg<0><<<ablocks, 256>>>();
    k_gemm2<<<gblocks, 256>>>(W2, b1);
    k_agg<1><<<ablocks, 256>>>();
    k_finish_pool<<<(N_NODES + 63) / 64, 256>>>(b2, batch);
    k_head<<<1, 256>>>(topo, Wlin, blin, out);
}

// round 6
// speedup vs baseline: 3.2999x; 1.3849x over previous
#include <cuda_runtime.h>
#include <cuda_fp16.h>

#define N_NODES 100000
#define N_EDGES 1600000
#define F 64
#define NUM_GRAPHS 64
#define TOPO_DIM 16
#define NUM_CLASSES 4

#define SCAN_BLK 512
#define SCAN_NBLK ((N_NODES + SCAN_BLK - 1) / SCAN_BLK)   // 196

// Scratch (device globals; allocation-free per harness rules)
__device__ int    g_cnt[N_NODES];
__device__ int    g_rowptr[N_NODES];
__device__ int    g_fill[N_NODES];
__device__ int    g_srcs[N_EDGES];
__device__ int    g_lscan[N_NODES];
__device__ int    g_bsum[SCAN_NBLK];
__device__ int    g_boff[SCAN_NBLK];
__device__ float  g_dis[N_NODES];
__device__ __half g_bufA[N_NODES * F];   // xs (fp16) — the gathered buffer
__device__ float  g_bufB[N_NODES * F];   // agg1 (fp32)
__device__ float  g_gsum[NUM_GRAPHS * F];
__device__ float  g_gcnt[NUM_GRAPHS];

// ---------------- init ----------------
__global__ void k_init() {
    int i = blockIdx.x * blockDim.x + threadIdx.x;
    if (i < N_NODES) g_cnt[i] = 0;
    if (i < NUM_GRAPHS * F) g_gsum[i] = 0.0f;
    if (i < NUM_GRAPHS) g_gcnt[i] = 0.0f;
}

// ---------------- degree histogram ----------------
__global__ void k_degree(const int* __restrict__ edge) {
    int e = blockIdx.x * blockDim.x + threadIdx.x;
    if (e < N_EDGES) atomicAdd(&g_cnt[edge[N_EDGES + e]], 1);
}

// ---------------- scan1 + dis + graph counts ----------------
__global__ void k_scan1(const int* __restrict__ batch) {
    __shared__ int s[SCAN_BLK];
    int t = threadIdx.x;
    int i = blockIdx.x * SCAN_BLK + t;
    int v = (i < N_NODES) ? g_cnt[i] : 0;
    if (i < N_NODES) {
        g_dis[i] = rsqrtf((float)v + 1.0f);
        atomicAdd(&g_gcnt[batch[i]], 1.0f);
    }
    s[t] = v;
    __syncthreads();
    #pragma unroll
    for (int off = 1; off < SCAN_BLK; off <<= 1) {
        int add = (t >= off) ? s[t - off] : 0;
        __syncthreads();
        s[t] += add;
        __syncthreads();
    }
    if (i < N_NODES) g_lscan[i] = s[t] - v;
    if (t == SCAN_BLK - 1) g_bsum[blockIdx.x] = s[t];
}

__global__ void k_scan2() {
    __shared__ int s[256];
    int t = threadIdx.x;
    int v = (t < SCAN_NBLK) ? g_bsum[t] : 0;
    s[t] = v;
    __syncthreads();
    #pragma unroll
    for (int off = 1; off < 256; off <<= 1) {
        int add = (t >= off) ? s[t - off] : 0;
        __syncthreads();
        s[t] += add;
        __syncthreads();
    }
    if (t < SCAN_NBLK) g_boff[t] = s[t] - v;
}

__global__ void k_scan3() {
    int i = blockIdx.x * blockDim.x + threadIdx.x;
    if (i < N_NODES) {
        int rp = g_lscan[i] + g_boff[i / SCAN_BLK];
        g_rowptr[i] = rp;
        g_fill[i] = rp;
    }
}

// ---------------- bin edges by dst ----------------
__global__ void k_bin(const int* __restrict__ edge) {
    int e = blockIdx.x * blockDim.x + threadIdx.x;
    if (e < N_EDGES) {
        int src = edge[e];
        int dst = edge[N_EDGES + e];
        int pos = atomicAdd(&g_fill[dst], 1);
        g_srcs[pos] = src;
    }
}

// ---------------- helpers ----------------
__device__ __forceinline__ void acc_half8(float* acc, uint4 u) {
    float2 f;
    f = __half22float2(*(__half2*)&u.x); acc[0] += f.x; acc[1] += f.y;
    f = __half22float2(*(__half2*)&u.y); acc[2] += f.x; acc[3] += f.y;
    f = __half22float2(*(__half2*)&u.z); acc[4] += f.x; acc[5] += f.y;
    f = __half22float2(*(__half2*)&u.w); acc[6] += f.x; acc[7] += f.y;
}

__device__ __forceinline__ void red_v4(float* p, float a, float b, float c, float d) {
    unsigned long long ga;
    asm("cvta.to.global.u64 %0, %1;" : "=l"(ga) : "l"(p));
    asm volatile("red.global.add.v4.f32 [%0], {%1,%2,%3,%4};"
                 :: "l"(ga), "f"(a), "f"(b), "f"(c), "f"(d) : "memory");
}

// ---------------- GEMM1: xs = (x @ W1) * dis -> fp16 ----------------
__global__ void k_gemm1(const float* __restrict__ x, const float* __restrict__ W) {
    __shared__ float Ws[F * F];
    __shared__ float Xs[64 * F];
    int tid = threadIdx.x;
    float4* Wv = (float4*)Ws;
    const float4* Wg = (const float4*)W;
    #pragma unroll
    for (int i = 0; i < 4; i++) Wv[tid + 256 * i] = Wg[tid + 256 * i];
    int base = blockIdx.x * 64;
    #pragma unroll
    for (int i = 0; i < 4; i++) {
        int idx = tid + 256 * i;
        int row = base + (idx >> 4);
        ((float4*)Xs)[idx] = (row < N_NODES)
            ? ((const float4*)x)[(long long)row * 16 + (idx & 15)]
            : make_float4(0.f, 0.f, 0.f, 0.f);
    }
    __syncthreads();
    int r4 = tid >> 4, c4 = tid & 15;
    float4 acc[4] = {};
    #pragma unroll
    for (int k = 0; k < F; k++) {
        float4 w = ((float4*)Ws)[k * 16 + c4];
        #pragma unroll
        for (int i = 0; i < 4; i++) {
            float xv = Xs[(r4 * 4 + i) * F + k];
            acc[i].x = fmaf(xv, w.x, acc[i].x);
            acc[i].y = fmaf(xv, w.y, acc[i].y);
            acc[i].z = fmaf(xv, w.z, acc[i].z);
            acc[i].w = fmaf(xv, w.w, acc[i].w);
        }
    }
    #pragma unroll
    for (int i = 0; i < 4; i++) {
        int row = base + r4 * 4 + i;
        if (row < N_NODES) {
            float dis = g_dis[row];
            __half2 ha = __floats2half2_rn(acc[i].x * dis, acc[i].y * dis);
            __half2 hb = __floats2half2_rn(acc[i].z * dis, acc[i].w * dis);
            uint2 u; *(__half2*)&u.x = ha; *(__half2*)&u.y = hb;
            ((uint2*)g_bufA)[row * 16 + c4] = u;
        }
    }
}

// ---------------- agg1: bufB[n] = sum_{src} xs[src]  (8 lanes x 16B, unroll-4) ----
__global__ void k_agg0() {
    int t = blockIdx.x * blockDim.x + threadIdx.x;
    int node = t >> 3;
    int lane = t & 7;
    if (node >= N_NODES) return;
    int beg = g_rowptr[node];
    int cnt = g_cnt[node];
    const uint4* A = (const uint4*)g_bufA;
    float acc[8] = {};
    int i = 0;
    for (; i + 4 <= cnt; i += 4) {
        int s0 = __ldg(&g_srcs[beg + i + 0]);
        int s1 = __ldg(&g_srcs[beg + i + 1]);
        int s2 = __ldg(&g_srcs[beg + i + 2]);
        int s3 = __ldg(&g_srcs[beg + i + 3]);
        uint4 u0 = __ldg(&A[s0 * 8 + lane]);
        uint4 u1 = __ldg(&A[s1 * 8 + lane]);
        uint4 u2 = __ldg(&A[s2 * 8 + lane]);
        uint4 u3 = __ldg(&A[s3 * 8 + lane]);
        acc_half8(acc, u0); acc_half8(acc, u1);
        acc_half8(acc, u2); acc_half8(acc, u3);
    }
    for (; i < cnt; i++) {
        int s = __ldg(&g_srcs[beg + i]);
        acc_half8(acc, __ldg(&A[s * 8 + lane]));
    }
    float4 lo = make_float4(acc[0], acc[1], acc[2], acc[3]);
    float4 hi = make_float4(acc[4], acc[5], acc[6], acc[7]);
    ((float4*)g_bufB)[node * 16 + lane * 2 + 0] = lo;
    ((float4*)g_bufB)[node * 16 + lane * 2 + 1] = hi;
}

// ---------------- GEMM2 fused: h = relu(dis*(agg+xs)+b1); xs2=(h@W2)*dis -> fp16
__global__ void k_gemm2(const float* __restrict__ W, const float* __restrict__ b1) {
    __shared__ float Ws[F * F];
    __shared__ float Hs[64 * F];
    int tid = threadIdx.x;
    float4* Wv = (float4*)Ws;
    const float4* Wg = (const float4*)W;
    #pragma unroll
    for (int i = 0; i < 4; i++) Wv[tid + 256 * i] = Wg[tid + 256 * i];
    int base = blockIdx.x * 64;
    #pragma unroll
    for (int i = 0; i < 4; i++) {
        int idx = tid + 256 * i;
        int row = base + (idx >> 4);
        int c = idx & 15;
        float4 h = make_float4(0.f, 0.f, 0.f, 0.f);
        if (row < N_NODES) {
            float dis = g_dis[row];
            float4 agg = ((const float4*)g_bufB)[(long long)row * 16 + c];
            uint2 xu = ((const uint2*)g_bufA)[row * 16 + c];
            float2 xa = __half22float2(*(__half2*)&xu.x);
            float2 xb = __half22float2(*(__half2*)&xu.y);
            float4 bb = ((const float4*)b1)[c];
            h.x = fmaxf(dis * (agg.x + xa.x) + bb.x, 0.0f);
            h.y = fmaxf(dis * (agg.y + xa.y) + bb.y, 0.0f);
            h.z = fmaxf(dis * (agg.z + xb.x) + bb.z, 0.0f);
            h.w = fmaxf(dis * (agg.w + xb.y) + bb.w, 0.0f);
        }
        ((float4*)Hs)[idx] = h;
    }
    __syncthreads();
    int r4 = tid >> 4, c4 = tid & 15;
    float4 acc[4] = {};
    #pragma unroll
    for (int k = 0; k < F; k++) {
        float4 w = ((float4*)Ws)[k * 16 + c4];
        #pragma unroll
        for (int i = 0; i < 4; i++) {
            float xv = Hs[(r4 * 4 + i) * F + k];
            acc[i].x = fmaf(xv, w.x, acc[i].x);
            acc[i].y = fmaf(xv, w.y, acc[i].y);
            acc[i].z = fmaf(xv, w.z, acc[i].z);
            acc[i].w = fmaf(xv, w.w, acc[i].w);
        }
    }
    #pragma unroll
    for (int i = 0; i < 4; i++) {
        int row = base + r4 * 4 + i;
        if (row < N_NODES) {
            float dis = g_dis[row];
            __half2 ha = __floats2half2_rn(acc[i].x * dis, acc[i].y * dis);
            __half2 hb = __floats2half2_rn(acc[i].z * dis, acc[i].w * dis);
            uint2 u; *(__half2*)&u.x = ha; *(__half2*)&u.y = hb;
            ((uint2*)g_bufA)[row * 16 + c4] = u;   // xs2 (reads done in phase 1)
        }
    }
}

// ---------------- agg2 fused with relu + mean-pool ----------------
// block = 256 threads = 32 nodes x 8 lanes. 100000/32 = 3125 blocks exact.
__global__ void k_agg1(const float* __restrict__ b2, const int* __restrict__ batch) {
    __shared__ float hacc[32 * F];   // 8KB
    int tid = threadIdx.x;
    int s = tid >> 3;                 // node-in-block 0..31
    int lane = tid & 7;
    int base = blockIdx.x * 32;
    int node = base + s;
    int beg = g_rowptr[node];
    int cnt = g_cnt[node];
    const uint4* A = (const uint4*)g_bufA;
    float acc[8] = {};
    int i = 0;
    for (; i + 4 <= cnt; i += 4) {
        int s0 = __ldg(&g_srcs[beg + i + 0]);
        int s1 = __ldg(&g_srcs[beg + i + 1]);
        int s2 = __ldg(&g_srcs[beg + i + 2]);
        int s3 = __ldg(&g_srcs[beg + i + 3]);
        uint4 u0 = __ldg(&A[s0 * 8 + lane]);
        uint4 u1 = __ldg(&A[s1 * 8 + lane]);
        uint4 u2 = __ldg(&A[s2 * 8 + lane]);
        uint4 u3 = __ldg(&A[s3 * 8 + lane]);
        acc_half8(acc, u0); acc_half8(acc, u1);
        acc_half8(acc, u2); acc_half8(acc, u3);
    }
    for (; i < cnt; i++) {
        int sidx = __ldg(&g_srcs[beg + i]);
        acc_half8(acc, __ldg(&A[sidx * 8 + lane]));
    }
    // self-loop + bias + relu
    float dis = g_dis[node];
    uint4 xu = __ldg(&A[node * 8 + lane]);
    float xs[8];
    {
        float2 f;
        f = __half22float2(*(__half2*)&xu.x); xs[0] = f.x; xs[1] = f.y;
        f = __half22float2(*(__half2*)&xu.y); xs[2] = f.x; xs[3] = f.y;
        f = __half22float2(*(__half2*)&xu.z); xs[4] = f.x; xs[5] = f.y;
        f = __half22float2(*(__half2*)&xu.w); xs[6] = f.x; xs[7] = f.y;
    }
    float h[8];
    #pragma unroll
    for (int j = 0; j < 8; j++)
        h[j] = fmaxf(dis * (acc[j] + xs[j]) + b2[lane * 8 + j], 0.0f);
    #pragma unroll
    for (int j = 0; j < 8; j++) hacc[s * F + lane * 8 + j] = h[j];
    __syncthreads();

    int g0 = batch[base];
    int g1 = batch[base + 31];
    if (g0 == g1) {
        // whole block in one graph: tree-reduce 32 rows, one red.v4 per 4 feats
        #pragma unroll
        for (int off = 16; off >= 1; off >>= 1) {
            if (s < off) {
                #pragma unroll
                for (int j = 0; j < 8; j++)
                    hacc[s * F + lane * 8 + j] += hacc[(s + off) * F + lane * 8 + j];
            }
            __syncthreads();
        }
        if (tid < 16) {
            float4 v = ((float4*)hacc)[tid];
            red_v4(&g_gsum[g0 * F + tid * 4], v.x, v.y, v.z, v.w);
        }
    } else {
        // boundary block: per-node reductions
        int g = batch[node];
        red_v4(&g_gsum[g * F + lane * 8 + 0], h[0], h[1], h[2], h[3]);
        red_v4(&g_gsum[g * F + lane * 8 + 4], h[4], h[5], h[6], h[7]);
    }
}

// ---------------- head ----------------
__global__ void k_head(const float* __restrict__ topo, const float* __restrict__ Wlin,
                       const float* __restrict__ blin, float* __restrict__ out) {
    int t = threadIdx.x;
    int g = t >> 2, c = t & 3;
    float inv = 1.0f / fmaxf(g_gcnt[g], 1.0f);
    float acc = blin[c];
    #pragma unroll
    for (int k = 0; k < F; k++)
        acc = fmaf(g_gsum[g * F + k] * inv, Wlin[k * NUM_CLASSES + c], acc);
    #pragma unroll
    for (int k = 0; k < TOPO_DIM; k++)
        acc = fmaf(topo[g * TOPO_DIM + k], Wlin[(F + k) * NUM_CLASSES + c], acc);
    out[g * NUM_CLASSES + c] = acc;
}

extern "C" void kernel_launch(void* const* d_in, const int* in_sizes, int n_in,
                              void* d_out, int out_size) {
    const float* x    = (const float*)d_in[0];
    const int*   edge = (const int*)d_in[1];
    const int*   batch= (const int*)d_in[2];
    const float* topo = (const float*)d_in[3];
    const float* W1   = (const float*)d_in[4];
    const float* b1   = (const float*)d_in[5];
    const float* W2   = (const float*)d_in[6];
    const float* b2   = (const float*)d_in[7];
    const float* Wlin = (const float*)d_in[8];
    const float* blin = (const float*)d_in[9];
    float* out = (float*)d_out;

    const int gblocks = (N_NODES + 63) / 64;          // 1563
    const int ablocks = N_NODES * 8 / 256;            // 3125 exact

    k_init<<<(N_NODES + 255) / 256, 256>>>();
    k_degree<<<(N_EDGES + 255) / 256, 256>>>(edge);
    k_scan1<<<SCAN_NBLK, SCAN_BLK>>>(batch);
    k_scan2<<<1, 256>>>();
    k_scan3<<<(N_NODES + 255) / 256, 256>>>();
    k_bin<<<(N_EDGES + 255) / 256, 256>>>(edge);

    k_gemm1<<<gblocks, 256>>>(x, W1);
    k_agg0<<<ablocks, 256>>>();
    k_gemm2<<<gblocks, 256>>>(W2, b1);
    k_agg1<<<ablocks, 256>>>(b2, batch);
    k_head<<<1, 256>>>(topo, Wlin, blin, out);
}